// round 3
// baseline (speedup 1.0000x reference)
#include <cuda_runtime.h>
#include <cstdint>

#define N_SEG 50000
#define D_FEAT 128
#define OUT_F 128
#define KDIM 256

// Scratch (allocation-free rule: __device__ globals)
__device__ float g_pooled[(size_t)N_SEG * KDIM];   // [N, 256] = 51.2 MB
__device__ int   g_starts[N_SEG + 1];
__device__ int   g_is64;

// ---------------------------------------------------------------------------
// Kernel -1: detect whether ids are int64 or int32.
// If int64 (little-endian, values < 2^31): every odd int32 word is 0.
// If int32: odd words in the middle of the sorted array are ids ~25000 (>0).
// All probed indices < M int32 words -> in-bounds for both layouts.
// ---------------------------------------------------------------------------
__global__ void detect_kernel(const int* __restrict__ ids32, int M) {
    int base = (M / 2) & ~1;           // even
    int nonzero = 0;
    for (int i = 1; i <= 63; i += 2) { // odd indices base+1 .. base+63
        if (base + i < M) nonzero |= ids32[base + i];
    }
    g_is64 = (nonzero == 0) ? 1 : 0;
}

// ---------------------------------------------------------------------------
// Kernel 0: segment boundaries from sorted ids (dtype-agnostic via g_is64).
// ---------------------------------------------------------------------------
__global__ void bounds_kernel(const int* __restrict__ ids32, int M, int Nseg) {
    int m = blockIdx.x * blockDim.x + threadIdx.x;
    if (m >= M) return;
    const long long* ids64 = (const long long*)ids32;
    int is64 = g_is64;

    long long id   = is64 ? ids64[m] : (long long)ids32[m];
    if (id < 0 || id >= Nseg) return;  // defensive clamp
    if (m == 0) {
        g_starts[id] = 0;
    } else {
        long long prev = is64 ? ids64[m - 1] : (long long)ids32[m - 1];
        if (prev != id) g_starts[id] = m;
    }
    if (m == M - 1) g_starts[Nseg] = M;
}

// ---------------------------------------------------------------------------
// Kernel 1: segmented max + mean. One block (128 threads) per segment;
// thread t owns feature column t -> every row read is one coalesced 512B line.
// ---------------------------------------------------------------------------
__global__ __launch_bounds__(128) void pool_kernel(const float* __restrict__ lane,
                                                   int M) {
    int seg = blockIdx.x;
    int col = threadIdx.x;
    int s = g_starts[seg];
    int e = g_starts[seg + 1];
    // defensive clamps
    if (s < 0) s = 0;
    if (e > M) e = M;
    int n = e - s;
    if (n <= 0) { // shouldn't happen: every id present
        float* dst0 = g_pooled + (size_t)seg * KDIM;
        dst0[col] = 0.f; dst0[D_FEAT + col] = 0.f;
        return;
    }

    const float* p = lane + (size_t)s * D_FEAT + col;
    float mx = -__int_as_float(0x7f800000);  // -inf
    float sm = 0.f;

    int r = 0;
    for (; r + 4 <= n; r += 4) {
        float a0 = p[(size_t)(r + 0) * D_FEAT];
        float a1 = p[(size_t)(r + 1) * D_FEAT];
        float a2 = p[(size_t)(r + 2) * D_FEAT];
        float a3 = p[(size_t)(r + 3) * D_FEAT];
        mx = fmaxf(mx, fmaxf(fmaxf(a0, a1), fmaxf(a2, a3)));
        sm += (a0 + a1) + (a2 + a3);
    }
    for (; r < n; r++) {
        float a = p[(size_t)r * D_FEAT];
        mx = fmaxf(mx, a);
        sm += a;
    }

    float* dst = g_pooled + (size_t)seg * KDIM;
    dst[col]          = mx;
    dst[D_FEAT + col] = sm / (float)n;
}

// ---------------------------------------------------------------------------
// Kernel 2: out = relu(pooled @ W^T + b).  A: [N,256], W: [128,256] row-major.
// Tile: 128 rows x 128 cols per block, K-chunks of 32, 8x8 per thread.
// ---------------------------------------------------------------------------
__global__ __launch_bounds__(256) void gemm_kernel(const float* __restrict__ W,
                                                   const float* __restrict__ b,
                                                   float* __restrict__ out,
                                                   int Nrows) {
    __shared__ float As[32][128 + 4];
    __shared__ float Ws[32][128 + 4];

    int tid = threadIdx.x;
    int row0 = blockIdx.x * 128;
    int tx = tid & 15;   // 16 col groups of 8
    int ty = tid >> 4;   // 16 row groups of 8

    float acc[8][8];
    #pragma unroll
    for (int i = 0; i < 8; i++)
        #pragma unroll
        for (int j = 0; j < 8; j++) acc[i][j] = 0.f;

    for (int kc = 0; kc < KDIM; kc += 32) {
        #pragma unroll
        for (int i = 0; i < 16; i++) {
            int idx = tid + i * 256;
            int rr = idx >> 5, kk = idx & 31;
            int grow = row0 + rr;
            As[kk][rr] = (grow < Nrows)
                       ? g_pooled[(size_t)grow * KDIM + kc + kk] : 0.f;
        }
        #pragma unroll
        for (int i = 0; i < 16; i++) {
            int idx = tid + i * 256;
            int oo = idx >> 5, kk = idx & 31;
            Ws[kk][oo] = W[(size_t)oo * KDIM + kc + kk];
        }
        __syncthreads();

        #pragma unroll
        for (int k = 0; k < 32; k++) {
            float a[8], w[8];
            #pragma unroll
            for (int i = 0; i < 8; i++) a[i] = As[k][ty * 8 + i];
            #pragma unroll
            for (int j = 0; j < 8; j++) w[j] = Ws[k][tx * 8 + j];
            #pragma unroll
            for (int i = 0; i < 8; i++)
                #pragma unroll
                for (int j = 0; j < 8; j++)
                    acc[i][j] = fmaf(a[i], w[j], acc[i][j]);
        }
        __syncthreads();
    }

    #pragma unroll
    for (int i = 0; i < 8; i++) {
        int grow = row0 + ty * 8 + i;
        if (grow >= Nrows) break;
        #pragma unroll
        for (int j = 0; j < 8; j++) {
            int o = tx * 8 + j;
            out[(size_t)grow * OUT_F + o] = fmaxf(acc[i][j] + b[o], 0.f);
        }
    }
}

extern "C" void kernel_launch(void* const* d_in, const int* in_sizes, int n_in,
                              void* d_out, int out_size) {
    // Identify inputs by element count (robust to metadata-order surprises):
    //   obs_encoding: 50000*128 = 6,400,000 f32
    //   lane_encoding: 800000*128 = 102,400,000 f32
    //   same_obs_mask: 800,000 ints
    //   W: 128*256 = 32,768 f32
    //   b: 128 f32
    const float* lane = nullptr;
    const int*   ids  = nullptr;
    const float* W    = nullptr;
    const float* bb   = nullptr;
    int M = 800000, Nseg = 50000;

    for (int i = 0; i < n_in; i++) {
        int sz = in_sizes[i];
        if (sz == 102400000)      lane = (const float*)d_in[i];
        else if (sz == 800000)  { ids  = (const int*)d_in[i]; M = sz; }
        else if (sz == 32768)     W    = (const float*)d_in[i];
        else if (sz == 128)       bb   = (const float*)d_in[i];
        else if (sz == 6400000)   Nseg = sz / D_FEAT;
    }
    // Fallback to positional if size matching failed
    if (!lane) lane = (const float*)d_in[1];
    if (!ids)  ids  = (const int*)d_in[2];
    if (!W)    W    = (const float*)d_in[3];
    if (!bb)   bb   = (const float*)d_in[4];

    float* out = (float*)d_out;

    detect_kernel<<<1, 1>>>(ids, M);
    bounds_kernel<<<(M + 255) / 256, 256>>>(ids, M, Nseg);
    pool_kernel<<<Nseg, 128>>>(lane, M);
    gemm_kernel<<<(Nseg + 127) / 128, 256>>>(W, bb, out, Nseg);
}